// round 1
// baseline (speedup 1.0000x reference)
#include <cuda_runtime.h>
#include <cuda_bf16.h>
#include <cstdint>

#define BATCH 32768
#define HDIM  512
#define MD    8
#define CDIM  1024
#define MVOC  1000
#define NCAT  262144
#define KDIM  532          // H + 20
#define KPAD  544          // padded to multiple of 32
#define EPS   1e-6f

// ---------------- static scratch (no allocations allowed) ----------------
__device__ float g_sums[BATCH * MD];          // segment sums            128 KB*8 = 1 MB
__device__ float g_counts[BATCH];             // segment counts          128 KB
__device__ float g_meta[BATCH * 20];          // meta features           2.5 MB
__device__ float g_bias[BATCH * 6];           // normalized credit vec   0.75 MB
__device__ float g_xln[(size_t)BATCH * KPAD]; // LN1 output, K-padded    ~71 MB
__device__ float g_wt[KPAD * CDIM];           // W1 transposed+padded    ~2.2 MB
__device__ float g_feat[(size_t)BATCH * CDIM];// hidden features         128 MB

// ---------------- helpers ----------------
__device__ __forceinline__ float warp_sum(float v) {
#pragma unroll
    for (int o = 16; o > 0; o >>= 1) v += __shfl_xor_sync(0xffffffffu, v, o);
    return v;
}

// ---------------- K0: zero segment scratch ----------------
__global__ void zero_kernel() {
    int i = blockIdx.x * blockDim.x + threadIdx.x;
    if (i < BATCH * MD) g_sums[i] = 0.0f;
    if (i < BATCH) g_counts[i] = 0.0f;
}

// ---------------- K1: ragged segment sum (cat ids sorted by segment) ----------------
__global__ void seg_kernel(const float* __restrict__ meta_table,
                           const int* __restrict__ cat_ids,
                           const int* __restrict__ cat_seg) {
    int i = blockIdx.x * blockDim.x + threadIdx.x;
    if (i >= NCAT) return;
    int c = cat_ids[i];
    int s = cat_seg[i];
    const float* e = meta_table + (size_t)c * MD;
#pragma unroll
    for (int d = 0; d < MD; d++) atomicAdd(&g_sums[s * MD + d], e[d]);
    atomicAdd(&g_counts[s], 1.0f);
}

// ---------------- K2: conv/relu/maxpool meta features + credit biases ----------------
__global__ void meta_kernel(const float* __restrict__ meta_table,
                            const float* __restrict__ conv_w,
                            const float* __restrict__ conv_b,
                            const int* __restrict__ meta_ids,
                            const float* __restrict__ credit) {
    int b = blockIdx.x * blockDim.x + threadIdx.x;
    if (b >= BATCH) return;

    float mat[6][MD];
    float cnt = fmaxf(g_counts[b], 1.0f);
#pragma unroll
    for (int d = 0; d < MD; d++) mat[0][d] = g_sums[b * MD + d] / cnt;
#pragma unroll
    for (int r = 0; r < 5; r++) {
        int id = meta_ids[b * 5 + r];
        const float* e = meta_table + (size_t)id * MD;
#pragma unroll
        for (int d = 0; d < MD; d++) mat[r + 1][d] = e[d];
    }

    // Conv1d(6->5, k=3, valid): out len 6, then ReLU
    float conv[5][6];
#pragma unroll
    for (int o = 0; o < 5; o++) {
#pragma unroll
        for (int t = 0; t < 6; t++) {
            float a = conv_b[o];
#pragma unroll
            for (int i = 0; i < 6; i++) {
#pragma unroll
                for (int k = 0; k < 3; k++)
                    a += mat[i][t + k] * conv_w[o * 18 + i * 3 + k];
            }
            conv[o][t] = fmaxf(a, 0.0f);
        }
    }
    // MaxPool1d(3, stride 1): out len 4, flatten [5,4]
#pragma unroll
    for (int o = 0; o < 5; o++) {
#pragma unroll
        for (int t = 0; t < 4; t++) {
            float m = fmaxf(fmaxf(conv[o][t], conv[o][t + 1]), conv[o][t + 2]);
            g_meta[b * 20 + o * 4 + t] = m;
        }
    }

    // biases = credit_vec / sum (uniform fallback if sum <= 0)
    float cv[6], s = 0.0f;
#pragma unroll
    for (int c = 0; c < 6; c++) { cv[c] = credit[b * 6 + c]; s += cv[c]; }
#pragma unroll
    for (int c = 0; c < 6; c++)
        g_bias[b * 6 + c] = (s > 0.0f) ? cv[c] / s : (1.0f / 6.0f);
}

// ---------------- K3: LN1 over concat(encode, meta_feat) -> g_xln padded ----------------
__global__ __launch_bounds__(256) void ln1_kernel(const float* __restrict__ encode,
                                                  const float* __restrict__ g1,
                                                  const float* __restrict__ b1) {
    int warp = threadIdx.x >> 5;
    int lane = threadIdx.x & 31;
    int row = blockIdx.x * 8 + warp;

    float v[17];
#pragma unroll
    for (int k = 0; k < 17; k++) {
        int j = k * 32 + lane;
        float x = 0.0f;
        if (j < HDIM)       x = encode[(size_t)row * HDIM + j];
        else if (j < KDIM)  x = g_meta[row * 20 + (j - HDIM)];
        v[k] = x;
    }
    float s = 0.0f;
#pragma unroll
    for (int k = 0; k < 17; k++) s += v[k];
    s = warp_sum(s);
    float mu = s * (1.0f / KDIM);

    float sq = 0.0f;
#pragma unroll
    for (int k = 0; k < 17; k++) {
        int j = k * 32 + lane;
        float d = (j < KDIM) ? (v[k] - mu) : 0.0f;
        sq += d * d;
    }
    sq = warp_sum(sq);
    float rs = rsqrtf(sq * (1.0f / KDIM) + EPS);

    float* dst = g_xln + (size_t)row * KPAD;
#pragma unroll
    for (int k = 0; k < 17; k++) {
        int j = k * 32 + lane;
        float y = 0.0f;
        if (j < KDIM) y = g1[j] * (v[k] - mu) * rs + b1[j];
        dst[j] = y;
    }
}

// ---------------- K4: transpose + zero-pad W1 -> g_wt[k][n] ----------------
__global__ void wt_kernel(const float* __restrict__ w) {
    int idx = blockIdx.x * blockDim.x + threadIdx.x;
    if (idx >= KPAD * CDIM) return;
    int k = idx / CDIM;
    int n = idx - k * CDIM;
    g_wt[idx] = (k < KDIM) ? w[(size_t)n * KDIM + k] : 0.0f;
}

// ---------------- K5: SGEMM  feat = relu(xln @ W^T + b)  (128x128x8 tiles) ----------------
__global__ __launch_bounds__(256) void gemm1_kernel(const float* __restrict__ bias) {
    __shared__ float As[8][128];
    __shared__ float Bs[8][128];

    int tid = threadIdx.x;
    int m0 = blockIdx.y * 128;
    int n0 = blockIdx.x * 128;

    int aRow = tid >> 1;            // 0..127
    int aCol = (tid & 1) * 4;       // 0 or 4
    int bRow = tid >> 5;            // 0..7
    int bCol = (tid & 31) * 4;      // 0..124

    const float* Aptr = g_xln + (size_t)(m0 + aRow) * KPAD + aCol;
    const float* Bptr = g_wt + (size_t)bRow * CDIM + n0 + bCol;

    int ty = tid >> 4;              // 0..15 -> rows
    int tx = tid & 15;              // 0..15 -> cols

    float acc[8][8];
#pragma unroll
    for (int i = 0; i < 8; i++)
#pragma unroll
        for (int j = 0; j < 8; j++) acc[i][j] = 0.0f;

    for (int k0 = 0; k0 < KPAD; k0 += 8) {
        float4 av = *(const float4*)(Aptr + k0);
        float4 bv = *(const float4*)(Bptr + (size_t)k0 * CDIM);
        As[aCol + 0][aRow] = av.x;
        As[aCol + 1][aRow] = av.y;
        As[aCol + 2][aRow] = av.z;
        As[aCol + 3][aRow] = av.w;
        *(float4*)&Bs[bRow][bCol] = bv;
        __syncthreads();

#pragma unroll
        for (int k = 0; k < 8; k++) {
            float a[8], b[8];
            *(float4*)(a)     = *(const float4*)&As[k][ty * 8];
            *(float4*)(a + 4) = *(const float4*)&As[k][ty * 8 + 4];
            *(float4*)(b)     = *(const float4*)&Bs[k][tx * 8];
            *(float4*)(b + 4) = *(const float4*)&Bs[k][tx * 8 + 4];
#pragma unroll
            for (int i = 0; i < 8; i++)
#pragma unroll
                for (int j = 0; j < 8; j++) acc[i][j] += a[i] * b[j];
        }
        __syncthreads();
    }

#pragma unroll
    for (int i = 0; i < 8; i++) {
        int m = m0 + ty * 8 + i;
        float* crow = g_feat + (size_t)m * CDIM + n0 + tx * 8;
#pragma unroll
        for (int j = 0; j < 8; j += 4) {
            int n = n0 + tx * 8 + j;
            float4 v;
            v.x = fmaxf(acc[i][j + 0] + bias[n + 0], 0.0f);
            v.y = fmaxf(acc[i][j + 1] + bias[n + 1], 0.0f);
            v.z = fmaxf(acc[i][j + 2] + bias[n + 2], 0.0f);
            v.w = fmaxf(acc[i][j + 3] + bias[n + 3], 0.0f);
            *(float4*)(crow + j) = v;
        }
    }
}

// ---------------- K6: LN2 + output GEMM (6 cols) + biases ----------------
__global__ __launch_bounds__(256) void out_kernel(const float* __restrict__ g2,
                                                  const float* __restrict__ b2,
                                                  const float* __restrict__ out_w,
                                                  const float* __restrict__ out_b,
                                                  float* __restrict__ out) {
    __shared__ float sw[6 * CDIM];
    for (int i = threadIdx.x; i < 6 * CDIM; i += 256) sw[i] = out_w[i];
    __syncthreads();

    int warp = threadIdx.x >> 5;
    int lane = threadIdx.x & 31;
    int row = blockIdx.x * 8 + warp;

    const float* f = g_feat + (size_t)row * CDIM;
    float v[32];
    float s = 0.0f;
#pragma unroll
    for (int k = 0; k < 32; k++) { v[k] = f[k * 32 + lane]; s += v[k]; }
    s = warp_sum(s);
    float mu = s * (1.0f / CDIM);

    float sq = 0.0f;
#pragma unroll
    for (int k = 0; k < 32; k++) { float d = v[k] - mu; sq += d * d; }
    sq = warp_sum(sq);
    float rs = rsqrtf(sq * (1.0f / CDIM) + EPS);

    float acc[6] = {0, 0, 0, 0, 0, 0};
#pragma unroll
    for (int k = 0; k < 32; k++) {
        int j = k * 32 + lane;
        float y = g2[j] * (v[k] - mu) * rs + b2[j];
#pragma unroll
        for (int c = 0; c < 6; c++) acc[c] += y * sw[c * CDIM + j];
    }
#pragma unroll
    for (int c = 0; c < 6; c++) acc[c] = warp_sum(acc[c]);

    if (lane == 0) {
#pragma unroll
        for (int c = 0; c < 6; c++)
            out[row * 6 + c] = acc[c] + out_b[c] + g_bias[row * 6 + c];
    }
}

// ---------------- launch ----------------
extern "C" void kernel_launch(void* const* d_in, const int* in_sizes, int n_in,
                              void* d_out, int out_size) {
    const float* encode     = (const float*)d_in[0];
    const float* credit_vec = (const float*)d_in[1];
    const float* meta_table = (const float*)d_in[2];
    const float* conv_w     = (const float*)d_in[3];
    const float* conv_b     = (const float*)d_in[4];
    const float* ln1_g      = (const float*)d_in[5];
    const float* ln1_b      = (const float*)d_in[6];
    const float* mlp1_w     = (const float*)d_in[7];
    const float* mlp1_b     = (const float*)d_in[8];
    const float* ln2_g      = (const float*)d_in[9];
    const float* ln2_b      = (const float*)d_in[10];
    const float* out_w      = (const float*)d_in[11];
    const float* out_b      = (const float*)d_in[12];
    const int*   meta_ids   = (const int*)d_in[13];
    const int*   cat_ids    = (const int*)d_in[14];
    const int*   cat_seg    = (const int*)d_in[15];
    float* out = (float*)d_out;

    zero_kernel<<<(BATCH * MD + 255) / 256, 256>>>();
    seg_kernel<<<(NCAT + 255) / 256, 256>>>(meta_table, cat_ids, cat_seg);
    meta_kernel<<<(BATCH + 127) / 128, 128>>>(meta_table, conv_w, conv_b, meta_ids, credit_vec);
    ln1_kernel<<<BATCH / 8, 256>>>(encode, ln1_g, ln1_b);
    wt_kernel<<<(KPAD * CDIM + 255) / 256, 256>>>(mlp1_w);
    {
        dim3 grid(CDIM / 128, BATCH / 128);
        gemm1_kernel<<<grid, 256>>>(mlp1_b);
    }
    out_kernel<<<BATCH / 8, 256>>>(ln2_g, ln2_b, out_w, out_b, out);
}

// round 3
// speedup vs baseline: 1.9448x; 1.9448x over previous
#include <cuda_runtime.h>
#include <cuda_bf16.h>
#include <cstdint>

#define BATCH 32768
#define HDIM  512
#define MD    8
#define CDIM  1024
#define NCAT  262144
#define KDIM  532
#define KP    576            // K padded to multiple of 32
#define NKIT  18             // KP / 32
#define EPS   1e-6f

// ---------------- static scratch ----------------
__device__ float g_sums[BATCH * MD];
__device__ float g_counts[BATCH];
__device__ float g_meta[BATCH * 20];
__device__ float g_bias6[BATCH * 6];
__device__ __nv_bfloat16 g_xhi[(size_t)BATCH * KP];   // 36 MB
__device__ __nv_bfloat16 g_xlo[(size_t)BATCH * KP];   // 36 MB
__device__ __nv_bfloat16 g_whi[CDIM * KP];
__device__ __nv_bfloat16 g_wlo[CDIM * KP];
__device__ float g_feat[(size_t)BATCH * CDIM];        // 128 MB

// ---------------- helpers ----------------
__device__ __forceinline__ float warp_sum(float v) {
#pragma unroll
    for (int o = 16; o > 0; o >>= 1) v += __shfl_xor_sync(0xffffffffu, v, o);
    return v;
}
__device__ __forceinline__ uint32_t smem_u32(const void* p) {
    uint32_t a;
    asm("{ .reg .u64 t; cvta.to.shared.u64 t, %1; cvt.u32.u64 %0, t; }" : "=r"(a) : "l"(p));
    return a;
}
__device__ __forceinline__ void cp8(uint32_t dst, const void* src) {
    unsigned long long g = (unsigned long long)__cvta_generic_to_global(src);
    asm volatile("cp.async.ca.shared.global [%0], [%1], 8;" :: "r"(dst), "l"(g) : "memory");
}
__device__ __forceinline__ void cp_commit() {
    asm volatile("cp.async.commit_group;" ::: "memory");
}
template <int N>
__device__ __forceinline__ void cp_wait() {
    asm volatile("cp.async.wait_group %0;" :: "n"(N) : "memory");
}
__device__ __forceinline__ void mma16816(float* d, const uint32_t* a, const uint32_t* b) {
    asm volatile(
        "mma.sync.aligned.m16n8k16.row.col.f32.bf16.bf16.f32 "
        "{%0,%1,%2,%3}, {%4,%5,%6,%7}, {%8,%9}, {%0,%1,%2,%3};"
        : "+f"(d[0]), "+f"(d[1]), "+f"(d[2]), "+f"(d[3])
        : "r"(a[0]), "r"(a[1]), "r"(a[2]), "r"(a[3]), "r"(b[0]), "r"(b[1]));
}
__device__ __forceinline__ void split_bf16(float x, __nv_bfloat16& h, __nv_bfloat16& l) {
    h = __float2bfloat16(x);
    l = __float2bfloat16(x - __bfloat162float(h));
}

// ---------------- K0: zero segment scratch ----------------
__global__ void zero_kernel() {
    int i = blockIdx.x * blockDim.x + threadIdx.x;
    if (i < BATCH * MD) g_sums[i] = 0.0f;
    if (i < BATCH) g_counts[i] = 0.0f;
}

// ---------------- K1: ragged segment sum ----------------
__global__ void seg_kernel(const float* __restrict__ meta_table,
                           const int* __restrict__ cat_ids,
                           const int* __restrict__ cat_seg) {
    int i = blockIdx.x * blockDim.x + threadIdx.x;
    if (i >= NCAT) return;
    int c = cat_ids[i];
    int s = cat_seg[i];
    const float* e = meta_table + (size_t)c * MD;
#pragma unroll
    for (int d = 0; d < MD; d++) atomicAdd(&g_sums[s * MD + d], e[d]);
    atomicAdd(&g_counts[s], 1.0f);
}

// ---------------- K2: conv/relu/maxpool + credit biases ----------------
__global__ void meta_kernel(const float* __restrict__ meta_table,
                            const float* __restrict__ conv_w,
                            const float* __restrict__ conv_b,
                            const int* __restrict__ meta_ids,
                            const float* __restrict__ credit) {
    int b = blockIdx.x * blockDim.x + threadIdx.x;
    if (b >= BATCH) return;

    float mat[6][MD];
    float cnt = fmaxf(g_counts[b], 1.0f);
#pragma unroll
    for (int d = 0; d < MD; d++) mat[0][d] = g_sums[b * MD + d] / cnt;
#pragma unroll
    for (int r = 0; r < 5; r++) {
        int id = meta_ids[b * 5 + r];
        const float* e = meta_table + (size_t)id * MD;
#pragma unroll
        for (int d = 0; d < MD; d++) mat[r + 1][d] = e[d];
    }
    float conv[5][6];
#pragma unroll
    for (int o = 0; o < 5; o++) {
#pragma unroll
        for (int t = 0; t < 6; t++) {
            float a = conv_b[o];
#pragma unroll
            for (int i = 0; i < 6; i++)
#pragma unroll
                for (int k = 0; k < 3; k++)
                    a += mat[i][t + k] * conv_w[o * 18 + i * 3 + k];
            conv[o][t] = fmaxf(a, 0.0f);
        }
    }
#pragma unroll
    for (int o = 0; o < 5; o++)
#pragma unroll
        for (int t = 0; t < 4; t++)
            g_meta[b * 20 + o * 4 + t] =
                fmaxf(fmaxf(conv[o][t], conv[o][t + 1]), conv[o][t + 2]);

    float cv[6], s = 0.0f;
#pragma unroll
    for (int c = 0; c < 6; c++) { cv[c] = credit[b * 6 + c]; s += cv[c]; }
#pragma unroll
    for (int c = 0; c < 6; c++)
        g_bias6[b * 6 + c] = (s > 0.0f) ? cv[c] / s : (1.0f / 6.0f);
}

// ---------------- K3: LN1 -> bf16 hi/lo, K padded to 576 ----------------
__global__ __launch_bounds__(256) void ln1_kernel(const float* __restrict__ encode,
                                                  const float* __restrict__ g1,
                                                  const float* __restrict__ b1) {
    int warp = threadIdx.x >> 5;
    int lane = threadIdx.x & 31;
    int row = blockIdx.x * 8 + warp;

    float v[17];
#pragma unroll
    for (int k = 0; k < 17; k++) {
        int j = k * 32 + lane;
        float x = 0.0f;
        if (j < HDIM)      x = encode[(size_t)row * HDIM + j];
        else if (j < KDIM) x = g_meta[row * 20 + (j - HDIM)];
        v[k] = x;
    }
    float s = 0.0f;
#pragma unroll
    for (int k = 0; k < 17; k++) s += v[k];
    s = warp_sum(s);
    float mu = s * (1.0f / KDIM);
    float sq = 0.0f;
#pragma unroll
    for (int k = 0; k < 17; k++) {
        int j = k * 32 + lane;
        float d = (j < KDIM) ? (v[k] - mu) : 0.0f;
        sq += d * d;
    }
    sq = warp_sum(sq);
    float rs = rsqrtf(sq * (1.0f / KDIM) + EPS);

    __nv_bfloat16* dh = g_xhi + (size_t)row * KP;
    __nv_bfloat16* dl = g_xlo + (size_t)row * KP;
#pragma unroll
    for (int k = 0; k < 18; k++) {
        int j = k * 32 + lane;
        float y = 0.0f;
        if (k < 17 && j < KDIM) y = g1[j] * (v[k] - mu) * rs + b1[j];
        __nv_bfloat16 h, l;
        split_bf16(y, h, l);
        dh[j] = h;
        dl[j] = l;
    }
}

// ---------------- K4: W1 -> bf16 hi/lo, padded ----------------
__global__ void wconv_kernel(const float* __restrict__ w) {
    int idx = blockIdx.x * blockDim.x + threadIdx.x;
    if (idx >= CDIM * KP) return;
    int n = idx / KP;
    int k = idx - n * KP;
    float v = (k < KDIM) ? w[(size_t)n * KDIM + k] : 0.0f;
    __nv_bfloat16 h, l;
    split_bf16(v, h, l);
    g_whi[idx] = h;
    g_wlo[idx] = l;
}

// ---------------- K5: bf16 mma.sync GEMM  feat = relu(x @ W^T + b) ----------------
// CTA tile 256x128, warp tile 64x64, K-step 32, 2-stage cp.async pipeline.
// SMEM row layout: [32 hi bf16 | 32 lo bf16 | 8B pad] = 144 B (36 words, conflict-free).
#define A_ROWS  256
#define B_ROWS  128
#define ROW_B   144
#define A_STG   (A_ROWS * ROW_B)           // 36864
#define B_STG   (B_ROWS * ROW_B)           // 18432
#define STG     (A_STG + B_STG)            // 55296
#define SMEM_TOT (2 * STG)                 // 110592

__global__ __launch_bounds__(256, 1) void gemm1_mma(const float* __restrict__ bias) {
    extern __shared__ char sm[];
    int tid = threadIdx.x;
    int lane = tid & 31;
    int w = tid >> 5;
    int wm = (w >> 1) * 64;     // warp M origin in CTA tile
    int wn = (w & 1) * 64;      // warp N origin

    int m0 = blockIdx.y * A_ROWS;
    int n0 = blockIdx.x * B_ROWS;

    uint32_t sbase = smem_u32(sm);

    float acc[4][8][4];
#pragma unroll
    for (int i = 0; i < 4; i++)
#pragma unroll
        for (int j = 0; j < 8; j++)
#pragma unroll
            for (int q = 0; q < 4; q++) acc[i][j][q] = 0.0f;

    // ---- stage loader (cp.async, 8B chunks) ----
    auto load_stage = [&](int st, int kc) {
        uint32_t sa = sbase + st * STG;
        uint32_t sb = sa + A_STG;
        int ko = kc * 32;
#pragma unroll
        for (int i = 0; i < 16; i++) {
            int idx = i * 256 + tid;
            int row = idx >> 4, sub = idx & 15;
            if (sub < 8) {
                cp8(sa + row * ROW_B + sub * 8,
                    g_xhi + (size_t)(m0 + row) * KP + ko + sub * 4);
            } else {
                cp8(sa + row * ROW_B + 64 + (sub - 8) * 8,
                    g_xlo + (size_t)(m0 + row) * KP + ko + (sub - 8) * 4);
            }
        }
#pragma unroll
        for (int i = 0; i < 8; i++) {
            int idx = i * 256 + tid;
            int row = idx >> 4, sub = idx & 15;
            if (sub < 8) {
                cp8(sb + row * ROW_B + sub * 8,
                    g_whi + (size_t)(n0 + row) * KP + ko + sub * 4);
            } else {
                cp8(sb + row * ROW_B + 64 + (sub - 8) * 8,
                    g_wlo + (size_t)(n0 + row) * KP + ko + (sub - 8) * 4);
            }
        }
        cp_commit();
    };

    load_stage(0, 0);

    int r = lane >> 2;           // 0..7
    int cbyte = (lane & 3) * 4;  // 0,4,8,12

    for (int kc = 0; kc < NKIT; kc++) {
        int cur = kc & 1;
        if (kc + 1 < NKIT) {
            load_stage((kc + 1) & 1, kc + 1);
            cp_wait<1>();
        } else {
            cp_wait<0>();
        }
        __syncthreads();

        const char* sa = sm + cur * STG;
        const char* sb = sa + A_STG;

#pragma unroll
        for (int kk = 0; kk < 2; kk++) {
            int kb = kk * 32;   // byte offset of k16 half within hi section
            uint32_t ah[4][4], al[4][4], bb[8][2];
            // A fragments (hi & lo)
#pragma unroll
            for (int i = 0; i < 4; i++) {
                const char* p0 = sa + (wm + i * 16 + r) * ROW_B + kb + cbyte;
                const char* p1 = sa + (wm + i * 16 + 8 + r) * ROW_B + kb + cbyte;
                ah[i][0] = *(const uint32_t*)(p0);
                ah[i][1] = *(const uint32_t*)(p1);
                ah[i][2] = *(const uint32_t*)(p0 + 16);
                ah[i][3] = *(const uint32_t*)(p1 + 16);
                al[i][0] = *(const uint32_t*)(p0 + 64);
                al[i][1] = *(const uint32_t*)(p1 + 64);
                al[i][2] = *(const uint32_t*)(p0 + 80);
                al[i][3] = *(const uint32_t*)(p1 + 80);
            }
            // B hi fragments
#pragma unroll
            for (int j = 0; j < 8; j++) {
                const char* p = sb + (wn + j * 8 + r) * ROW_B + kb + cbyte;
                bb[j][0] = *(const uint32_t*)(p);
                bb[j][1] = *(const uint32_t*)(p + 16);
            }
#pragma unroll
            for (int i = 0; i < 4; i++)
#pragma unroll
                for (int j = 0; j < 8; j++) {
                    mma16816(acc[i][j], ah[i], bb[j]);
                    mma16816(acc[i][j], al[i], bb[j]);
                }
            // B lo fragments (reuse regs)
#pragma unroll
            for (int j = 0; j < 8; j++) {
                const char* p = sb + (wn + j * 8 + r) * ROW_B + kb + cbyte + 64;
                bb[j][0] = *(const uint32_t*)(p);
                bb[j][1] = *(const uint32_t*)(p + 16);
            }
#pragma unroll
            for (int i = 0; i < 4; i++)
#pragma unroll
                for (int j = 0; j < 8; j++)
                    mma16816(acc[i][j], ah[i], bb[j]);
        }
        __syncthreads();
    }

    // ---- epilogue: bias + relu -> g_feat ----
#pragma unroll
    for (int i = 0; i < 4; i++) {
        int row = m0 + wm + i * 16 + r;
#pragma unroll
        for (int j = 0; j < 8; j++) {
            int col = n0 + wn + j * 8 + (lane & 3) * 2;
            float b0 = bias[col], b1 = bias[col + 1];
            float2 v0, v1;
            v0.x = fmaxf(acc[i][j][0] + b0, 0.0f);
            v0.y = fmaxf(acc[i][j][1] + b1, 0.0f);
            v1.x = fmaxf(acc[i][j][2] + b0, 0.0f);
            v1.y = fmaxf(acc[i][j][3] + b1, 0.0f);
            *(float2*)(g_feat + (size_t)row * CDIM + col) = v0;
            *(float2*)(g_feat + (size_t)(row + 8) * CDIM + col) = v1;
        }
    }
}

// ---------------- K6: LN2 + output GEMM (6 cols) + biases ----------------
__global__ __launch_bounds__(256) void out_kernel(const float* __restrict__ g2,
                                                  const float* __restrict__ b2,
                                                  const float* __restrict__ out_w,
                                                  const float* __restrict__ out_b,
                                                  float* __restrict__ out) {
    __shared__ float sw[6 * CDIM];
    for (int i = threadIdx.x; i < 6 * CDIM; i += 256) sw[i] = out_w[i];
    __syncthreads();

    int warp = threadIdx.x >> 5;
    int lane = threadIdx.x & 31;
    int row = blockIdx.x * 8 + warp;

    const float* f = g_feat + (size_t)row * CDIM;
    float v[32];
    float s = 0.0f;
#pragma unroll
    for (int k = 0; k < 32; k++) { v[k] = f[k * 32 + lane]; s += v[k]; }
    s = warp_sum(s);
    float mu = s * (1.0f / CDIM);
    float sq = 0.0f;
#pragma unroll
    for (int k = 0; k < 32; k++) { float d = v[k] - mu; sq += d * d; }
    sq = warp_sum(sq);
    float rs = rsqrtf(sq * (1.0f / CDIM) + EPS);

    float acc[6] = {0, 0, 0, 0, 0, 0};
#pragma unroll
    for (int k = 0; k < 32; k++) {
        int j = k * 32 + lane;
        float y = g2[j] * (v[k] - mu) * rs + b2[j];
#pragma unroll
        for (int c = 0; c < 6; c++) acc[c] += y * sw[c * CDIM + j];
    }
#pragma unroll
    for (int c = 0; c < 6; c++) acc[c] = warp_sum(acc[c]);

    if (lane == 0) {
#pragma unroll
        for (int c = 0; c < 6; c++)
            out[row * 6 + c] = acc[c] + out_b[c] + g_bias6[row * 6 + c];
    }
}

// ---------------- launch ----------------
extern "C" void kernel_launch(void* const* d_in, const int* in_sizes, int n_in,
                              void* d_out, int out_size) {
    const float* encode     = (const float*)d_in[0];
    const float* credit_vec = (const float*)d_in[1];
    const float* meta_table = (const float*)d_in[2];
    const float* conv_w     = (const float*)d_in[3];
    const float* conv_b     = (const float*)d_in[4];
    const float* ln1_g      = (const float*)d_in[5];
    const float* ln1_b      = (const float*)d_in[6];
    const float* mlp1_w     = (const float*)d_in[7];
    const float* mlp1_b     = (const float*)d_in[8];
    const float* ln2_g      = (const float*)d_in[9];
    const float* ln2_b      = (const float*)d_in[10];
    const float* out_w      = (const float*)d_in[11];
    const float* out_b      = (const float*)d_in[12];
    const int*   meta_ids   = (const int*)d_in[13];
    const int*   cat_ids    = (const int*)d_in[14];
    const int*   cat_seg    = (const int*)d_in[15];
    float* out = (float*)d_out;

    static bool init = false;
    if (!init) {
        cudaFuncSetAttribute(gemm1_mma, cudaFuncAttributeMaxDynamicSharedMemorySize, SMEM_TOT);
        init = true;
    }

    zero_kernel<<<(BATCH * MD + 255) / 256, 256>>>();
    seg_kernel<<<(NCAT + 255) / 256, 256>>>(meta_table, cat_ids, cat_seg);
    meta_kernel<<<(BATCH + 127) / 128, 128>>>(meta_table, conv_w, conv_b, meta_ids, credit_vec);
    ln1_kernel<<<BATCH / 8, 256>>>(encode, ln1_g, ln1_b);
    wconv_kernel<<<(CDIM * KP + 255) / 256, 256>>>(mlp1_w);
    {
        dim3 grid(CDIM / B_ROWS, BATCH / A_ROWS);   // (8, 128)
        gemm1_mma<<<grid, 256, SMEM_TOT>>>(mlp1_b);
    }
    out_kernel<<<BATCH / 8, 256>>>(ln2_g, ln2_b, out_w, out_b, out);
}

// round 4
// speedup vs baseline: 2.1135x; 1.0868x over previous
#include <cuda_runtime.h>
#include <cuda_bf16.h>
#include <cstdint>

#define BATCH 32768
#define HDIM  512
#define MD    8
#define CDIM  1024
#define NCAT  262144
#define KDIM  532
#define KP    576            // K padded to multiple of 32
#define NKIT  18             // KP / 32
#define EPS   1e-6f

// ---------------- static scratch ----------------
__device__ float g_sums[BATCH * MD];
__device__ float g_counts[BATCH];
__device__ float g_meta[BATCH * 20];
__device__ float g_bias6[BATCH * 6];
__device__ __nv_bfloat16 g_xhi[(size_t)BATCH * KP];   // 36 MB
__device__ __nv_bfloat16 g_xlo[(size_t)BATCH * KP];   // 36 MB
__device__ __nv_bfloat16 g_whi[CDIM * KP];
__device__ __nv_bfloat16 g_wlo[CDIM * KP];
__device__ float g_feat[(size_t)BATCH * CDIM];        // 128 MB

// ---------------- helpers ----------------
__device__ __forceinline__ float warp_sum(float v) {
#pragma unroll
    for (int o = 16; o > 0; o >>= 1) v += __shfl_xor_sync(0xffffffffu, v, o);
    return v;
}
__device__ __forceinline__ uint32_t smem_u32(const void* p) {
    uint32_t a;
    asm("{ .reg .u64 t; cvta.to.shared.u64 t, %1; cvt.u32.u64 %0, t; }" : "=r"(a) : "l"(p));
    return a;
}
__device__ __forceinline__ void cp16(uint32_t dst, const void* src) {
    unsigned long long g = (unsigned long long)__cvta_generic_to_global(src);
    asm volatile("cp.async.cg.shared.global [%0], [%1], 16;" :: "r"(dst), "l"(g) : "memory");
}
__device__ __forceinline__ void cp_commit() {
    asm volatile("cp.async.commit_group;" ::: "memory");
}
template <int N>
__device__ __forceinline__ void cp_wait() {
    asm volatile("cp.async.wait_group %0;" :: "n"(N) : "memory");
}
__device__ __forceinline__ void ldsm4(uint32_t* r, uint32_t addr) {
    asm volatile("ldmatrix.sync.aligned.m8n8.x4.shared.b16 {%0,%1,%2,%3}, [%4];"
                 : "=r"(r[0]), "=r"(r[1]), "=r"(r[2]), "=r"(r[3]) : "r"(addr));
}
__device__ __forceinline__ void mma16816(float* d, const uint32_t* a, const uint32_t* b) {
    asm volatile(
        "mma.sync.aligned.m16n8k16.row.col.f32.bf16.bf16.f32 "
        "{%0,%1,%2,%3}, {%4,%5,%6,%7}, {%8,%9}, {%0,%1,%2,%3};"
        : "+f"(d[0]), "+f"(d[1]), "+f"(d[2]), "+f"(d[3])
        : "r"(a[0]), "r"(a[1]), "r"(a[2]), "r"(a[3]), "r"(b[0]), "r"(b[1]));
}
__device__ __forceinline__ void split_bf16(float x, __nv_bfloat16& h, __nv_bfloat16& l) {
    h = __float2bfloat16(x);
    l = __float2bfloat16(x - __bfloat162float(h));
}

// ---------------- K0: zero segment scratch ----------------
__global__ void zero_kernel() {
    int i = blockIdx.x * blockDim.x + threadIdx.x;
    if (i < BATCH * MD) g_sums[i] = 0.0f;
    if (i < BATCH) g_counts[i] = 0.0f;
}

// ---------------- K1: ragged segment sum ----------------
__global__ void seg_kernel(const float* __restrict__ meta_table,
                           const int* __restrict__ cat_ids,
                           const int* __restrict__ cat_seg) {
    int i = blockIdx.x * blockDim.x + threadIdx.x;
    if (i >= NCAT) return;
    int c = cat_ids[i];
    int s = cat_seg[i];
    const float* e = meta_table + (size_t)c * MD;
#pragma unroll
    for (int d = 0; d < MD; d++) atomicAdd(&g_sums[s * MD + d], e[d]);
    atomicAdd(&g_counts[s], 1.0f);
}

// ---------------- K2: conv/relu/maxpool + credit biases ----------------
__global__ void meta_kernel(const float* __restrict__ meta_table,
                            const float* __restrict__ conv_w,
                            const float* __restrict__ conv_b,
                            const int* __restrict__ meta_ids,
                            const float* __restrict__ credit) {
    int b = blockIdx.x * blockDim.x + threadIdx.x;
    if (b >= BATCH) return;

    float mat[6][MD];
    float cnt = fmaxf(g_counts[b], 1.0f);
#pragma unroll
    for (int d = 0; d < MD; d++) mat[0][d] = g_sums[b * MD + d] / cnt;
#pragma unroll
    for (int r = 0; r < 5; r++) {
        int id = meta_ids[b * 5 + r];
        const float* e = meta_table + (size_t)id * MD;
#pragma unroll
        for (int d = 0; d < MD; d++) mat[r + 1][d] = e[d];
    }
    float conv[5][6];
#pragma unroll
    for (int o = 0; o < 5; o++) {
#pragma unroll
        for (int t = 0; t < 6; t++) {
            float a = conv_b[o];
#pragma unroll
            for (int i = 0; i < 6; i++)
#pragma unroll
                for (int k = 0; k < 3; k++)
                    a += mat[i][t + k] * conv_w[o * 18 + i * 3 + k];
            conv[o][t] = fmaxf(a, 0.0f);
        }
    }
#pragma unroll
    for (int o = 0; o < 5; o++)
#pragma unroll
        for (int t = 0; t < 4; t++)
            g_meta[b * 20 + o * 4 + t] =
                fmaxf(fmaxf(conv[o][t], conv[o][t + 1]), conv[o][t + 2]);

    float cv[6], s = 0.0f;
#pragma unroll
    for (int c = 0; c < 6; c++) { cv[c] = credit[b * 6 + c]; s += cv[c]; }
#pragma unroll
    for (int c = 0; c < 6; c++)
        g_bias6[b * 6 + c] = (s > 0.0f) ? cv[c] / s : (1.0f / 6.0f);
}

// ---------------- K3: LN1 -> bf16 hi/lo, K padded to 576 ----------------
__global__ __launch_bounds__(256) void ln1_kernel(const float* __restrict__ encode,
                                                  const float* __restrict__ g1,
                                                  const float* __restrict__ b1) {
    int warp = threadIdx.x >> 5;
    int lane = threadIdx.x & 31;
    int row = blockIdx.x * 8 + warp;

    float v[17];
#pragma unroll
    for (int k = 0; k < 17; k++) {
        int j = k * 32 + lane;
        float x = 0.0f;
        if (j < HDIM)      x = encode[(size_t)row * HDIM + j];
        else if (j < KDIM) x = g_meta[row * 20 + (j - HDIM)];
        v[k] = x;
    }
    float s = 0.0f;
#pragma unroll
    for (int k = 0; k < 17; k++) s += v[k];
    s = warp_sum(s);
    float mu = s * (1.0f / KDIM);
    float sq = 0.0f;
#pragma unroll
    for (int k = 0; k < 17; k++) {
        int j = k * 32 + lane;
        float d = (j < KDIM) ? (v[k] - mu) : 0.0f;
        sq += d * d;
    }
    sq = warp_sum(sq);
    float rs = rsqrtf(sq * (1.0f / KDIM) + EPS);

    __nv_bfloat16* dh = g_xhi + (size_t)row * KP;
    __nv_bfloat16* dl = g_xlo + (size_t)row * KP;
#pragma unroll
    for (int k = 0; k < 18; k++) {
        int j = k * 32 + lane;
        float y = 0.0f;
        if (k < 17 && j < KDIM) y = g1[j] * (v[k] - mu) * rs + b1[j];
        __nv_bfloat16 h, l;
        split_bf16(y, h, l);
        dh[j] = h;
        dl[j] = l;
    }
}

// ---------------- K4: W1 -> bf16 hi/lo, padded ----------------
__global__ void wconv_kernel(const float* __restrict__ w) {
    int idx = blockIdx.x * blockDim.x + threadIdx.x;
    if (idx >= CDIM * KP) return;
    int n = idx / KP;
    int k = idx - n * KP;
    float v = (k < KDIM) ? w[(size_t)n * KDIM + k] : 0.0f;
    __nv_bfloat16 h, l;
    split_bf16(v, h, l);
    g_whi[idx] = h;
    g_wlo[idx] = l;
}

// ---------------- K5: bf16 mma.sync GEMM with ldmatrix + 3-stage cp.async ----------------
// CTA tile 256x128, warp tile 64x64, K-step 32.
// SMEM row: [32 hi bf16 | 32 lo bf16 | 16B pad] = 144 B (36 words, LDSM conflict-free).
#define A_ROWS  256
#define B_ROWS  128
#define ROW_B   144
#define A_STG   (A_ROWS * ROW_B)           // 36864
#define B_STG   (B_ROWS * ROW_B)           // 18432
#define STG     (A_STG + B_STG)            // 55296
#define NSTAGE  3
#define SMEM_TOT (NSTAGE * STG)            // 165888

__global__ __launch_bounds__(256, 1) void gemm1_mma(const float* __restrict__ bias) {
    extern __shared__ char sm[];
    int tid = threadIdx.x;
    int lane = tid & 31;
    int w = tid >> 5;
    int wm = (w >> 1) * 64;     // warp M origin
    int wn = (w & 1) * 64;      // warp N origin

    int m0 = blockIdx.y * A_ROWS;
    int n0 = blockIdx.x * B_ROWS;

    uint32_t sbase = smem_u32(sm);

    float acc[4][8][4];
#pragma unroll
    for (int i = 0; i < 4; i++)
#pragma unroll
        for (int j = 0; j < 8; j++)
#pragma unroll
            for (int q = 0; q < 4; q++) acc[i][j][q] = 0.0f;

    // ---- stage loader: 16B cp.async chunks ----
    auto load_stage = [&](int st, int kc) {
        uint32_t sa = sbase + st * STG;
        uint32_t sb = sa + A_STG;
        int ko = kc * 32;
        // A: 256 rows x (4 hi + 4 lo) 16B chunks = 2048 -> 8/thread
#pragma unroll
        for (int i = 0; i < 8; i++) {
            int idx = i * 256 + tid;
            int row = idx >> 3, c = idx & 7;
            uint32_t dst = sa + row * ROW_B + ((c < 4) ? c * 16 : 64 + (c - 4) * 16);
            const __nv_bfloat16* src = ((c < 4) ? g_xhi : g_xlo)
                                       + (size_t)(m0 + row) * KP + ko + (c & 3) * 8;
            cp16(dst, src);
        }
        // B: 128 rows x 8 chunks = 1024 -> 4/thread
#pragma unroll
        for (int i = 0; i < 4; i++) {
            int idx = i * 256 + tid;
            int row = idx >> 3, c = idx & 7;
            uint32_t dst = sb + row * ROW_B + ((c < 4) ? c * 16 : 64 + (c - 4) * 16);
            const __nv_bfloat16* src = ((c < 4) ? g_whi : g_wlo)
                                       + (size_t)(n0 + row) * KP + ko + (c & 3) * 8;
            cp16(dst, src);
        }
        cp_commit();
    };

    load_stage(0, 0);
    load_stage(1, 1);

    // ldmatrix per-lane offsets
    int a_lrow = lane & 15;            // row within m16 tile
    int a_lcol = (lane >> 4) * 16;     // 0 or 16 (k 0-7 vs 8-15)
    int b_lrow = (lane & 7) + ((lane >> 4) & 1) * 8;  // n within n16 tile
    int b_lcol = ((lane >> 3) & 1) * 16;

    for (int kc = 0; kc < NKIT; kc++) {
        if (kc + 2 < NKIT) { load_stage((kc + 2) % NSTAGE, kc + 2); cp_wait<2>(); }
        else if (kc + 1 < NKIT) cp_wait<1>();
        else cp_wait<0>();
        __syncthreads();

        uint32_t sa = sbase + (kc % NSTAGE) * STG;
        uint32_t sb = sa + A_STG;

#pragma unroll
        for (int kk = 0; kk < 2; kk++) {
            int kb = kk * 32;   // byte offset of k16 half
            uint32_t ah[4][4], al[4][4], bb[8][2];
#pragma unroll
            for (int i = 0; i < 4; i++) {
                uint32_t base = sa + (wm + i * 16 + a_lrow) * ROW_B + kb + a_lcol;
                ldsm4(ah[i], base);
                ldsm4(al[i], base + 64);
            }
            // B hi
#pragma unroll
            for (int jj = 0; jj < 4; jj++) {
                uint32_t base = sb + (wn + jj * 16 + b_lrow) * ROW_B + kb + b_lcol;
                uint32_t t[4];
                ldsm4(t, base);
                bb[jj * 2][0] = t[0]; bb[jj * 2][1] = t[1];
                bb[jj * 2 + 1][0] = t[2]; bb[jj * 2 + 1][1] = t[3];
            }
#pragma unroll
            for (int i = 0; i < 4; i++)
#pragma unroll
                for (int j = 0; j < 8; j++) mma16816(acc[i][j], ah[i], bb[j]);
#pragma unroll
            for (int i = 0; i < 4; i++)
#pragma unroll
                for (int j = 0; j < 8; j++) mma16816(acc[i][j], al[i], bb[j]);
            // B lo (reuse bb)
#pragma unroll
            for (int jj = 0; jj < 4; jj++) {
                uint32_t base = sb + (wn + jj * 16 + b_lrow) * ROW_B + kb + b_lcol + 64;
                uint32_t t[4];
                ldsm4(t, base);
                bb[jj * 2][0] = t[0]; bb[jj * 2][1] = t[1];
                bb[jj * 2 + 1][0] = t[2]; bb[jj * 2 + 1][1] = t[3];
            }
#pragma unroll
            for (int i = 0; i < 4; i++)
#pragma unroll
                for (int j = 0; j < 8; j++) mma16816(acc[i][j], ah[i], bb[j]);
        }
        __syncthreads();
    }

    // ---- epilogue: bias + relu -> g_feat ----
    int r = lane >> 2;
#pragma unroll
    for (int i = 0; i < 4; i++) {
        int row = m0 + wm + i * 16 + r;
#pragma unroll
        for (int j = 0; j < 8; j++) {
            int col = n0 + wn + j * 8 + (lane & 3) * 2;
            float b0 = bias[col], b1 = bias[col + 1];
            float2 v0, v1;
            v0.x = fmaxf(acc[i][j][0] + b0, 0.0f);
            v0.y = fmaxf(acc[i][j][1] + b1, 0.0f);
            v1.x = fmaxf(acc[i][j][2] + b0, 0.0f);
            v1.y = fmaxf(acc[i][j][3] + b1, 0.0f);
            *(float2*)(g_feat + (size_t)row * CDIM + col) = v0;
            *(float2*)(g_feat + (size_t)(row + 8) * CDIM + col) = v1;
        }
    }
}

// ---------------- K6: LN2 + output GEMM (6 cols) + biases ----------------
__global__ __launch_bounds__(256) void out_kernel(const float* __restrict__ g2,
                                                  const float* __restrict__ b2,
                                                  const float* __restrict__ out_w,
                                                  const float* __restrict__ out_b,
                                                  float* __restrict__ out) {
    __shared__ float sw[6 * CDIM];
    for (int i = threadIdx.x; i < 6 * CDIM; i += 256) sw[i] = out_w[i];
    __syncthreads();

    int warp = threadIdx.x >> 5;
    int lane = threadIdx.x & 31;
    int row = blockIdx.x * 8 + warp;

    const float* f = g_feat + (size_t)row * CDIM;
    float v[32];
    float s = 0.0f;
#pragma unroll
    for (int k = 0; k < 32; k++) { v[k] = f[k * 32 + lane]; s += v[k]; }
    s = warp_sum(s);
    float mu = s * (1.0f / CDIM);
    float sq = 0.0f;
#pragma unroll
    for (int k = 0; k < 32; k++) { float d = v[k] - mu; sq += d * d; }
    sq = warp_sum(sq);
    float rs = rsqrtf(sq * (1.0f / CDIM) + EPS);

    float acc[6] = {0, 0, 0, 0, 0, 0};
#pragma unroll
    for (int k = 0; k < 32; k++) {
        int j = k * 32 + lane;
        float y = g2[j] * (v[k] - mu) * rs + b2[j];
#pragma unroll
        for (int c = 0; c < 6; c++) acc[c] += y * sw[c * CDIM + j];
    }
#pragma unroll
    for (int c = 0; c < 6; c++) acc[c] = warp_sum(acc[c]);

    if (lane == 0) {
#pragma unroll
        for (int c = 0; c < 6; c++)
            out[row * 6 + c] = acc[c] + out_b[c] + g_bias6[row * 6 + c];
    }
}

// ---------------- launch ----------------
extern "C" void kernel_launch(void* const* d_in, const int* in_sizes, int n_in,
                              void* d_out, int out_size) {
    const float* encode     = (const float*)d_in[0];
    const float* credit_vec = (const float*)d_in[1];
    const float* meta_table = (const float*)d_in[2];
    const float* conv_w     = (const float*)d_in[3];
    const float* conv_b     = (const float*)d_in[4];
    const float* ln1_g      = (const float*)d_in[5];
    const float* ln1_b      = (const float*)d_in[6];
    const float* mlp1_w     = (const float*)d_in[7];
    const float* mlp1_b     = (const float*)d_in[8];
    const float* ln2_g      = (const float*)d_in[9];
    const float* ln2_b      = (const float*)d_in[10];
    const float* out_w      = (const float*)d_in[11];
    const float* out_b      = (const float*)d_in[12];
    const int*   meta_ids   = (const int*)d_in[13];
    const int*   cat_ids    = (const int*)d_in[14];
    const int*   cat_seg    = (const int*)d_in[15];
    float* out = (float*)d_out;

    static bool init = false;
    if (!init) {
        cudaFuncSetAttribute(gemm1_mma, cudaFuncAttributeMaxDynamicSharedMemorySize, SMEM_TOT);
        init = true;
    }

    zero_kernel<<<(BATCH * MD + 255) / 256, 256>>>();
    seg_kernel<<<(NCAT + 255) / 256, 256>>>(meta_table, cat_ids, cat_seg);
    meta_kernel<<<(BATCH + 127) / 128, 128>>>(meta_table, conv_w, conv_b, meta_ids, credit_vec);
    ln1_kernel<<<BATCH / 8, 256>>>(encode, ln1_g, ln1_b);
    wconv_kernel<<<(CDIM * KP + 255) / 256, 256>>>(mlp1_w);
    {
        dim3 grid(CDIM / B_ROWS, BATCH / A_ROWS);   // (8, 128)
        gemm1_mma<<<grid, 256, SMEM_TOT>>>(mlp1_b);
    }
    out_kernel<<<BATCH / 8, 256>>>(ln2_g, ln2_b, out_w, out_b, out);
}